// round 1
// baseline (speedup 1.0000x reference)
#include <cuda_runtime.h>
#include <math.h>

#define BATCH 16384
#define DIM   1024
#define FFN   4096
#define NHEAD 16
#define HDIM  64

// ---------------- scratch (static device globals; no runtime allocs) -------
__device__ float g_mavg[(size_t)BATCH * DIM];
__device__ float g_qin [(size_t)BATCH * DIM];
__device__ float g_q   [(size_t)BATCH * DIM];
__device__ float g_k0  [(size_t)BATCH * DIM];
__device__ float g_k1  [(size_t)BATCH * DIM];
__device__ float g_k2  [(size_t)BATCH * DIM];
__device__ float g_v0  [(size_t)BATCH * DIM];
__device__ float g_v1  [(size_t)BATCH * DIM];
__device__ float g_v2  [(size_t)BATCH * DIM];
__device__ float g_x   [(size_t)BATCH * DIM];
__device__ float g_h1  [(size_t)BATCH * FFN];
__device__ float g_y   [(size_t)BATCH * DIM];

// ---------------- elementwise: mavg = (m0+m1+m2)/3 --------------------------
__global__ void mavg_kernel(const float4* __restrict__ m0,
                            const float4* __restrict__ m1,
                            const float4* __restrict__ m2,
                            float4* __restrict__ out, int n4)
{
    int i = blockIdx.x * blockDim.x + threadIdx.x;
    if (i < n4) {
        float4 a = m0[i], b = m1[i], c = m2[i];
        const float s = 1.0f / 3.0f;
        float4 r;
        r.x = (a.x + b.x + c.x) * s;
        r.y = (a.y + b.y + c.y) * s;
        r.z = (a.z + b.z + c.z) * s;
        r.w = (a.w + b.w + c.w) * s;
        out[i] = r;
    }
}

// ---------------- SGEMM: D = A[M,K] @ W[K,N] + bias (+C) (relu) -------------
// MODE 0: D = A@W + bias
// MODE 1: D = A@W + bias + C
// MODE 2: D = relu(A@W + bias)
#define BM 128
#define BN 128
#define BK 8
#define TM 8
#define TN 8

template<int MODE>
__global__ __launch_bounds__(256)
void sgemm_kernel(const float* __restrict__ A, const float* __restrict__ W,
                  const float* __restrict__ bias, const float* __restrict__ C,
                  float* __restrict__ D, int M, int N, int K)
{
    __shared__ float As[BK][BM];
    __shared__ float Bs[BK][BN];

    const int tid = threadIdx.x;
    const int bm = blockIdx.y * BM;
    const int bn = blockIdx.x * BN;

    const int a_row = tid >> 1;          // 0..127
    const int a_col = (tid & 1) << 2;    // 0 or 4
    const int b_row = tid >> 5;          // 0..7
    const int b_col = (tid & 31) << 2;   // 0..124

    const int ty = tid >> 4;             // 0..15
    const int tx = tid & 15;             // 0..15

    float acc[TM][TN];
    #pragma unroll
    for (int i = 0; i < TM; i++)
        #pragma unroll
        for (int j = 0; j < TN; j++) acc[i][j] = 0.0f;

    const float* Ap = A + (size_t)(bm + a_row) * K + a_col;
    const float* Wp = W + (size_t)b_row * N + bn + b_col;

    for (int k0 = 0; k0 < K; k0 += BK) {
        float4 av = *(const float4*)(Ap + k0);
        As[a_col + 0][a_row] = av.x;
        As[a_col + 1][a_row] = av.y;
        As[a_col + 2][a_row] = av.z;
        As[a_col + 3][a_row] = av.w;
        float4 wv = *(const float4*)(Wp + (size_t)k0 * N);
        *(float4*)&Bs[b_row][b_col] = wv;
        __syncthreads();

        #pragma unroll
        for (int kk = 0; kk < BK; kk++) {
            float ar[TM], br[TN];
            #pragma unroll
            for (int i = 0; i < TM; i++) ar[i] = As[kk][ty * TM + i];
            #pragma unroll
            for (int j = 0; j < TN; j++) br[j] = Bs[kk][tx * TN + j];
            #pragma unroll
            for (int i = 0; i < TM; i++)
                #pragma unroll
                for (int j = 0; j < TN; j++)
                    acc[i][j] += ar[i] * br[j];
        }
        __syncthreads();
    }

    #pragma unroll
    for (int i = 0; i < TM; i++) {
        const int gm = bm + ty * TM + i;
        float*       drow = D + (size_t)gm * N + bn + tx * TN;
        const float* crow = (MODE == 1) ? (C + (size_t)gm * N + bn + tx * TN) : nullptr;
        #pragma unroll
        for (int j = 0; j < TN; j++) {
            float v = acc[i][j] + bias[bn + tx * TN + j];
            if (MODE == 1) v += crow[j];
            if (MODE == 2) v = fmaxf(v, 0.0f);
            drow[j] = v;
        }
    }
}

// ---------------- attention over 3 keys + residual + LN1 --------------------
// one block (256 threads) per row; each thread owns 4 contiguous floats
__global__ __launch_bounds__(256)
void attn_ln1_kernel(const float* __restrict__ q,
                     const float* __restrict__ k0, const float* __restrict__ k1,
                     const float* __restrict__ k2,
                     const float* __restrict__ v0, const float* __restrict__ v1,
                     const float* __restrict__ v2,
                     const float* __restrict__ dom,
                     const float* __restrict__ gam, const float* __restrict__ bet,
                     float* __restrict__ x)
{
    const int b = blockIdx.x;
    const int t = threadIdx.x;
    const size_t off = (size_t)b * DIM + 4 * t;

    float4 q4 = *(const float4*)(q  + off);
    float4 ka = *(const float4*)(k0 + off);
    float4 kb = *(const float4*)(k1 + off);
    float4 kc = *(const float4*)(k2 + off);

    float s0 = q4.x*ka.x + q4.y*ka.y + q4.z*ka.z + q4.w*ka.w;
    float s1 = q4.x*kb.x + q4.y*kb.y + q4.z*kb.z + q4.w*kb.w;
    float s2 = q4.x*kc.x + q4.y*kc.y + q4.z*kc.z + q4.w*kc.w;

    // reduce per head: head = 64 floats = 16 threads (width-16 segments)
    #pragma unroll
    for (int o = 8; o; o >>= 1) {
        s0 += __shfl_xor_sync(0xffffffffu, s0, o, 16);
        s1 += __shfl_xor_sync(0xffffffffu, s1, o, 16);
        s2 += __shfl_xor_sync(0xffffffffu, s2, o, 16);
    }
    const float sc = 0.125f;  // 1/sqrt(64)
    s0 *= sc; s1 *= sc; s2 *= sc;
    float mx = fmaxf(s0, fmaxf(s1, s2));
    float e0 = expf(s0 - mx), e1 = expf(s1 - mx), e2 = expf(s2 - mx);
    float inv = 1.0f / (e0 + e1 + e2);
    e0 *= inv; e1 *= inv; e2 *= inv;

    float4 va = *(const float4*)(v0 + off);
    float4 vb = *(const float4*)(v1 + off);
    float4 vc = *(const float4*)(v2 + off);
    float4 d4 = *(const float4*)(dom + off);

    float4 r;
    r.x = d4.x + e0*va.x + e1*vb.x + e2*vc.x;
    r.y = d4.y + e0*va.y + e1*vb.y + e2*vc.y;
    r.z = d4.z + e0*va.z + e1*vb.z + e2*vc.z;
    r.w = d4.w + e0*va.w + e1*vb.w + e2*vc.w;

    // LayerNorm over the 1024-row
    float sum = r.x + r.y + r.z + r.w;
    float sq  = r.x*r.x + r.y*r.y + r.z*r.z + r.w*r.w;
    #pragma unroll
    for (int o = 16; o; o >>= 1) {
        sum += __shfl_xor_sync(0xffffffffu, sum, o);
        sq  += __shfl_xor_sync(0xffffffffu, sq,  o);
    }
    __shared__ float red[16];
    const int w = t >> 5;
    if ((t & 31) == 0) { red[w] = sum; red[8 + w] = sq; }
    __syncthreads();
    if (t == 0) {
        float a = 0.f, c = 0.f;
        #pragma unroll
        for (int i = 0; i < 8; i++) { a += red[i]; c += red[8 + i]; }
        red[0] = a; red[8] = c;
    }
    __syncthreads();
    sum = red[0]; sq = red[8];

    const float mu  = sum * (1.0f / DIM);
    const float var = sq * (1.0f / DIM) - mu * mu;
    const float rs  = rsqrtf(var + 1e-5f);

    float4 gg = *(const float4*)(gam + 4 * t);
    float4 bb = *(const float4*)(bet + 4 * t);
    float4 xo;
    xo.x = (r.x - mu) * rs * gg.x + bb.x;
    xo.y = (r.y - mu) * rs * gg.y + bb.y;
    xo.z = (r.z - mu) * rs * gg.z + bb.z;
    xo.w = (r.w - mu) * rs * gg.w + bb.w;
    *(float4*)(x + off) = xo;
}

// ---------------- LN2 + 3-logit head + softmax ------------------------------
__global__ __launch_bounds__(256)
void ln2_head_kernel(const float* __restrict__ y,
                     const float* __restrict__ gam, const float* __restrict__ bet,
                     const float* __restrict__ Ww, const float* __restrict__ bw,
                     float* __restrict__ out)
{
    const int b = blockIdx.x;
    const int t = threadIdx.x;
    const size_t off = (size_t)b * DIM + 4 * t;

    float4 r = *(const float4*)(y + off);
    float sum = r.x + r.y + r.z + r.w;
    float sq  = r.x*r.x + r.y*r.y + r.z*r.z + r.w*r.w;
    #pragma unroll
    for (int o = 16; o; o >>= 1) {
        sum += __shfl_xor_sync(0xffffffffu, sum, o);
        sq  += __shfl_xor_sync(0xffffffffu, sq,  o);
    }
    __shared__ float red[24];
    const int w = t >> 5;
    if ((t & 31) == 0) { red[w] = sum; red[8 + w] = sq; }
    __syncthreads();
    if (t == 0) {
        float a = 0.f, c = 0.f;
        #pragma unroll
        for (int i = 0; i < 8; i++) { a += red[i]; c += red[8 + i]; }
        red[0] = a; red[8] = c;
    }
    __syncthreads();
    sum = red[0]; sq = red[8];

    const float mu  = sum * (1.0f / DIM);
    const float var = sq * (1.0f / DIM) - mu * mu;
    const float rs  = rsqrtf(var + 1e-5f);

    float4 gg = *(const float4*)(gam + 4 * t);
    float4 bb = *(const float4*)(bet + 4 * t);
    float xn[4];
    xn[0] = (r.x - mu) * rs * gg.x + bb.x;
    xn[1] = (r.y - mu) * rs * gg.y + bb.y;
    xn[2] = (r.z - mu) * rs * gg.z + bb.z;
    xn[3] = (r.w - mu) * rs * gg.w + bb.w;

    float l0 = 0.f, l1 = 0.f, l2 = 0.f;
    const int base = 4 * t;
    #pragma unroll
    for (int e = 0; e < 4; e++) {
        const float* wr = Ww + (size_t)(base + e) * 3;
        l0 += xn[e] * wr[0];
        l1 += xn[e] * wr[1];
        l2 += xn[e] * wr[2];
    }
    #pragma unroll
    for (int o = 16; o; o >>= 1) {
        l0 += __shfl_xor_sync(0xffffffffu, l0, o);
        l1 += __shfl_xor_sync(0xffffffffu, l1, o);
        l2 += __shfl_xor_sync(0xffffffffu, l2, o);
    }
    __syncthreads();   // red reuse barrier
    if ((t & 31) == 0) { red[w] = l0; red[8 + w] = l1; red[16 + w] = l2; }
    __syncthreads();
    if (t == 0) {
        float a = 0.f, c = 0.f, d = 0.f;
        #pragma unroll
        for (int i = 0; i < 8; i++) { a += red[i]; c += red[8 + i]; d += red[16 + i]; }
        a += bw[0]; c += bw[1]; d += bw[2];
        float m = fmaxf(a, fmaxf(c, d));
        float e0 = expf(a - m), e1 = expf(c - m), e2 = expf(d - m);
        float inv = 1.0f / (e0 + e1 + e2);
        out[3 * (size_t)b + 0] = e0 * inv;
        out[3 * (size_t)b + 1] = e1 * inv;
        out[3 * (size_t)b + 2] = e2 * inv;
    }
}

// ---------------- launch ----------------------------------------------------
extern "C" void kernel_launch(void* const* d_in, const int* in_sizes, int n_in,
                              void* d_out, int out_size)
{
    const float* m0   = (const float*)d_in[0];
    const float* m1   = (const float*)d_in[1];
    const float* m2   = (const float*)d_in[2];
    const float* dom  = (const float*)d_in[3];
    const float* Wg   = (const float*)d_in[4];
    const float* bg   = (const float*)d_in[5];
    const float* Wq   = (const float*)d_in[6];
    const float* bq   = (const float*)d_in[7];
    const float* Wk   = (const float*)d_in[8];
    const float* bk   = (const float*)d_in[9];
    const float* Wv   = (const float*)d_in[10];
    const float* bv   = (const float*)d_in[11];
    const float* W1   = (const float*)d_in[12];
    const float* b1   = (const float*)d_in[13];
    const float* W2   = (const float*)d_in[14];
    const float* b2   = (const float*)d_in[15];
    const float* gm1  = (const float*)d_in[16];
    const float* bt1  = (const float*)d_in[17];
    const float* gm2  = (const float*)d_in[18];
    const float* bt2  = (const float*)d_in[19];
    const float* Ww   = (const float*)d_in[20];
    const float* bw   = (const float*)d_in[21];
    float* out = (float*)d_out;

    float *mavg, *qin, *q, *k0, *k1, *k2, *v0, *v1, *v2, *x, *h1, *y;
    cudaGetSymbolAddress((void**)&mavg, g_mavg);
    cudaGetSymbolAddress((void**)&qin,  g_qin);
    cudaGetSymbolAddress((void**)&q,    g_q);
    cudaGetSymbolAddress((void**)&k0,   g_k0);
    cudaGetSymbolAddress((void**)&k1,   g_k1);
    cudaGetSymbolAddress((void**)&k2,   g_k2);
    cudaGetSymbolAddress((void**)&v0,   g_v0);
    cudaGetSymbolAddress((void**)&v1,   g_v1);
    cudaGetSymbolAddress((void**)&v2,   g_v2);
    cudaGetSymbolAddress((void**)&x,    g_x);
    cudaGetSymbolAddress((void**)&h1,   g_h1);
    cudaGetSymbolAddress((void**)&y,    g_y);

    const int n4 = BATCH * DIM / 4;
    mavg_kernel<<<(n4 + 255) / 256, 256>>>((const float4*)m0, (const float4*)m1,
                                           (const float4*)m2, (float4*)mavg, n4);

    dim3 blk(256);
    dim3 grid_d(DIM / BN, BATCH / BM);   // (8, 128)
    dim3 grid_f(FFN / BN, BATCH / BM);   // (32, 128)

    // qin = mavg@Wg + bg + domain   (fused residual)
    sgemm_kernel<1><<<grid_d, blk>>>(mavg, Wg, bg, dom, qin, BATCH, DIM, DIM);
    // q = qin@Wq + bq
    sgemm_kernel<0><<<grid_d, blk>>>(qin, Wq, bq, nullptr, q, BATCH, DIM, DIM);
    // k_i = m_i@Wk + bk ; v_i = m_i@Wv + bv
    sgemm_kernel<0><<<grid_d, blk>>>(m0, Wk, bk, nullptr, k0, BATCH, DIM, DIM);
    sgemm_kernel<0><<<grid_d, blk>>>(m1, Wk, bk, nullptr, k1, BATCH, DIM, DIM);
    sgemm_kernel<0><<<grid_d, blk>>>(m2, Wk, bk, nullptr, k2, BATCH, DIM, DIM);
    sgemm_kernel<0><<<grid_d, blk>>>(m0, Wv, bv, nullptr, v0, BATCH, DIM, DIM);
    sgemm_kernel<0><<<grid_d, blk>>>(m1, Wv, bv, nullptr, v1, BATCH, DIM, DIM);
    sgemm_kernel<0><<<grid_d, blk>>>(m2, Wv, bv, nullptr, v2, BATCH, DIM, DIM);

    // attention + residual + LN1 -> x
    attn_ln1_kernel<<<BATCH, 256>>>(q, k0, k1, k2, v0, v1, v2, dom, gm1, bt1, x);

    // h1 = relu(x@W1 + b1)
    sgemm_kernel<2><<<grid_f, blk>>>(x, W1, b1, nullptr, h1, BATCH, FFN, DIM);
    // y = x + h1@W2 + b2   (fused residual)
    sgemm_kernel<1><<<grid_d, blk>>>(h1, W2, b2, x, y, BATCH, DIM, FFN);

    // LN2 + 3-logit head + softmax -> out
    ln2_head_kernel<<<BATCH, 256>>>(y, gm2, bt2, Ww, bw, out);
}

// round 3
// speedup vs baseline: 3.1688x; 3.1688x over previous
#include <cuda_runtime.h>
#include <cuda_bf16.h>
#include <stdint.h>
#include <math.h>

#define BATCH 16384
#define DIM   1024
#define FFN   4096

#define NB ((size_t)BATCH * DIM)
#define NF ((size_t)BATCH * FFN)

// ---------------- scratch (static device globals; no runtime allocs) -------
__device__ __nv_bfloat16 g_mavgh[NB], g_mavgl[NB];
__device__ __nv_bfloat16 g_m0h[NB],   g_m0l[NB];
__device__ __nv_bfloat16 g_m1h[NB],   g_m1l[NB];
__device__ __nv_bfloat16 g_m2h[NB],   g_m2l[NB];
__device__ __nv_bfloat16 g_qinh[NB],  g_qinl[NB];
__device__ __nv_bfloat16 g_xh[NB],    g_xl[NB];
__device__ __nv_bfloat16 g_h1h[NF],   g_h1l[NF];
// transposed + split weights, [N,K] K-major
__device__ __nv_bfloat16 g_Wgth[(size_t)DIM*DIM], g_Wgtl[(size_t)DIM*DIM];
__device__ __nv_bfloat16 g_Wqth[(size_t)DIM*DIM], g_Wqtl[(size_t)DIM*DIM];
__device__ __nv_bfloat16 g_Wkth[(size_t)DIM*DIM], g_Wktl[(size_t)DIM*DIM];
__device__ __nv_bfloat16 g_Wvth[(size_t)DIM*DIM], g_Wvtl[(size_t)DIM*DIM];
__device__ __nv_bfloat16 g_W1th[(size_t)DIM*FFN], g_W1tl[(size_t)DIM*FFN];
__device__ __nv_bfloat16 g_W2th[(size_t)DIM*FFN], g_W2tl[(size_t)DIM*FFN];
// fp32 intermediates
__device__ float g_q[NB], g_k0[NB], g_k1[NB], g_k2[NB];
__device__ float g_v0[NB], g_v1[NB], g_v2[NB];
__device__ float g_x[NB], g_y[NB];

// ---------------- helpers ----------------------------------------------------
__device__ __forceinline__ uint32_t s2u(const void* p) {
    uint32_t a;
    asm("{ .reg .u64 t; cvta.to.shared.u64 t, %1; cvt.u32.u64 %0, t; }" : "=r"(a) : "l"(p));
    return a;
}
__device__ __forceinline__ void cp16(uint32_t s, const void* g) {
    asm volatile("cp.async.cg.shared.global [%0], [%1], 16;" :: "r"(s), "l"(g));
}
#define SWZ(o) ((o) ^ (((o) >> 3) & 0x70))

__device__ __forceinline__ void ldsm4(uint32_t addr, uint32_t* r) {
    asm volatile("ldmatrix.sync.aligned.m8n8.x4.shared.b16 {%0,%1,%2,%3}, [%4];"
        : "=r"(r[0]), "=r"(r[1]), "=r"(r[2]), "=r"(r[3]) : "r"(addr));
}
__device__ __forceinline__ void mma16816(float* c, const uint32_t* a, const uint32_t* b) {
    asm volatile(
        "mma.sync.aligned.m16n8k16.row.col.f32.bf16.bf16.f32 "
        "{%0,%1,%2,%3}, {%4,%5,%6,%7}, {%8,%9}, {%0,%1,%2,%3};"
        : "+f"(c[0]), "+f"(c[1]), "+f"(c[2]), "+f"(c[3])
        : "r"(a[0]), "r"(a[1]), "r"(a[2]), "r"(a[3]), "r"(b[0]), "r"(b[1]));
}
__device__ __forceinline__ void split1(float v, __nv_bfloat16& h, __nv_bfloat16& l) {
    h = __float2bfloat16(v);
    l = __float2bfloat16(v - __bfloat162float(h));
}

// ---------------- prep: split m0/m1/m2 + mavg (single pass) -----------------
__global__ void prep_kernel(const float4* __restrict__ m0, const float4* __restrict__ m1,
                            const float4* __restrict__ m2,
                            __nv_bfloat162* __restrict__ m0h, __nv_bfloat162* __restrict__ m0l,
                            __nv_bfloat162* __restrict__ m1h, __nv_bfloat162* __restrict__ m1l,
                            __nv_bfloat162* __restrict__ m2h, __nv_bfloat162* __restrict__ m2l,
                            __nv_bfloat162* __restrict__ avh, __nv_bfloat162* __restrict__ avl,
                            int n4)
{
    int i = blockIdx.x * blockDim.x + threadIdx.x;
    if (i >= n4) return;
    float4 a = m0[i], b = m1[i], c = m2[i];
    const float s = 1.0f / 3.0f;
    float4 v;
    v.x = (a.x+b.x+c.x)*s; v.y = (a.y+b.y+c.y)*s;
    v.z = (a.z+b.z+c.z)*s; v.w = (a.w+b.w+c.w)*s;
    #define DOSPLIT(src, H, L) { \
        __nv_bfloat16 h0,h1,h2,h3,l0,l1,l2,l3; \
        split1(src.x,h0,l0); split1(src.y,h1,l1); split1(src.z,h2,l2); split1(src.w,h3,l3); \
        H[2*i] = __halves2bfloat162(h0,h1); H[2*i+1] = __halves2bfloat162(h2,h3); \
        L[2*i] = __halves2bfloat162(l0,l1); L[2*i+1] = __halves2bfloat162(l2,l3); }
    DOSPLIT(a, m0h, m0l);
    DOSPLIT(b, m1h, m1l);
    DOSPLIT(c, m2h, m2l);
    DOSPLIT(v, avh, avl);
    #undef DOSPLIT
}

// weights: W[K,N] fp32 -> out [N,K] bf16 hi/lo (transpose + split)
__global__ void wtrans_kernel(const float* __restrict__ W,
                              __nv_bfloat16* __restrict__ H, __nv_bfloat16* __restrict__ L,
                              int K, int N)
{
    __shared__ float t[32][33];
    const int k0 = blockIdx.y << 5, n0 = blockIdx.x << 5;
    const int tx = threadIdx.x, ty = threadIdx.y;
    #pragma unroll
    for (int r = 0; r < 32; r += 8)
        t[ty + r][tx] = W[(size_t)(k0 + ty + r) * N + n0 + tx];
    __syncthreads();
    #pragma unroll
    for (int r = 0; r < 32; r += 8) {
        float v = t[tx][ty + r];
        __nv_bfloat16 h, l; split1(v, h, l);
        size_t o = (size_t)(n0 + ty + r) * K + k0 + tx;
        H[o] = h; L[o] = l;
    }
}

// ---------------- split-bf16 HMMA GEMM ---------------------------------------
// D[M,N] = (Ahi+Alo)[M,K] @ (Bhi+Blo)[N,K]^T + bias (+C) (relu)
// MODE 0: +bias; MODE 1: +bias+C; MODE 2: relu(+bias)
#define SMEM_SZ (3 * 65536)

// load one 128x64 bf16 tile (row-major [*,K]) into SW128-swizzled SMEM (256 thr)
__device__ __forceinline__ void ldtile(uint32_t sbase, const __nv_bfloat16* g, int ldk, int tid) {
    #pragma unroll
    for (int i = 0; i < 4; i++) {
        int idx = tid + (i << 8);
        int row = idx >> 3, ks = idx & 7;
        cp16(sbase + SWZ(row * 128 + ks * 16), g + (size_t)row * ldk + ks * 8);
    }
}

template<int MODE, bool SPLIT>
__global__ __launch_bounds__(256, 1)
void mma_gemm(const __nv_bfloat16* __restrict__ Ah, const __nv_bfloat16* __restrict__ Al,
              const __nv_bfloat16* __restrict__ Bh, const __nv_bfloat16* __restrict__ Bl,
              const float* __restrict__ bias, const float* __restrict__ Cres,
              float* __restrict__ Dout,
              __nv_bfloat16* __restrict__ Dhi, __nv_bfloat16* __restrict__ Dlo,
              int N, int K)
{
    extern __shared__ char smem[];
    const uint32_t sb = s2u(smem);
    const int tid = threadIdx.x;
    const int wid = tid >> 5, lane = tid & 31;
    const int bm = blockIdx.y << 7, bn = blockIdx.x << 7;
    const int wm = (wid >> 1) << 5;   // warp row offset 0/32/64/96
    const int wn = (wid & 1) << 6;    // warp col offset 0/64
    const int nch = K >> 6;

    const __nv_bfloat16* Ahp = Ah + (size_t)bm * K;
    const __nv_bfloat16* Alp = Al + (size_t)bm * K;
    const __nv_bfloat16* Bhp = Bh + (size_t)bn * K;
    const __nv_bfloat16* Blp = Bl + (size_t)bn * K;

    // prologue: chunks 0,1 -> stages 0,1
    #pragma unroll
    for (int c = 0; c < 2; c++) {
        uint32_t st = sb + c * 65536;
        ldtile(st,         Ahp + c * 64, K, tid);
        ldtile(st + 16384, Alp + c * 64, K, tid);
        ldtile(st + 32768, Bhp + c * 64, K, tid);
        ldtile(st + 49152, Blp + c * 64, K, tid);
        asm volatile("cp.async.commit_group;" ::: "memory");
    }

    float acc[2][8][4];
    #pragma unroll
    for (int a = 0; a < 2; a++)
        #pragma unroll
        for (int b = 0; b < 8; b++)
            #pragma unroll
            for (int d = 0; d < 4; d++) acc[a][b][d] = 0.0f;

    // ldmatrix per-lane addressing
    const int aRow = wm + (lane & 15);
    const int aKB  = ((lane >> 4) & 1) * 16;
    const int bj   = lane >> 3;
    const int bRow = wn + ((bj >> 1) << 3) + (lane & 7);
    const int bKB  = (bj & 1) * 16;

    for (int i = 0; i < nch; i++) {
        if (i < nch - 1) asm volatile("cp.async.wait_group 1;" ::: "memory");
        else             asm volatile("cp.async.wait_group 0;" ::: "memory");
        __syncthreads();

        // prefetch chunk i+2 (overlaps with compute below)
        const int pc = i + 2;
        if (pc < nch) {
            uint32_t pt = sb + (pc % 3) * 65536;
            ldtile(pt,         Ahp + pc * 64, K, tid);
            ldtile(pt + 16384, Alp + pc * 64, K, tid);
            ldtile(pt + 32768, Bhp + pc * 64, K, tid);
            ldtile(pt + 49152, Blp + pc * 64, K, tid);
            asm volatile("cp.async.commit_group;" ::: "memory");
        }

        const uint32_t st = sb + (i % 3) * 65536;
        #pragma unroll
        for (int kk = 0; kk < 4; kk++) {
            uint32_t aH[2][4], aL[2][4];
            #pragma unroll
            for (int tm = 0; tm < 2; tm++) {
                uint32_t off = SWZ((uint32_t)((aRow + tm * 16) * 128 + kk * 32 + aKB));
                ldsm4(st + off,         aH[tm]);
                ldsm4(st + 16384 + off, aL[tm]);
            }
            uint32_t bH[4][4], bL[4][4];
            #pragma unroll
            for (int p = 0; p < 4; p++) {
                uint32_t off = SWZ((uint32_t)((bRow + p * 16) * 128 + kk * 32 + bKB));
                ldsm4(st + 32768 + off, bH[p]);
                ldsm4(st + 49152 + off, bL[p]);
            }
            #pragma unroll
            for (int tm = 0; tm < 2; tm++)
                #pragma unroll
                for (int p = 0; p < 4; p++) {
                    mma16816(acc[tm][2*p],     aH[tm], &bH[p][0]);
                    mma16816(acc[tm][2*p + 1], aH[tm], &bH[p][2]);
                    mma16816(acc[tm][2*p],     aH[tm], &bL[p][0]);
                    mma16816(acc[tm][2*p + 1], aH[tm], &bL[p][2]);
                    mma16816(acc[tm][2*p],     aL[tm], &bH[p][0]);
                    mma16816(acc[tm][2*p + 1], aL[tm], &bH[p][2]);
                }
        }
    }

    // epilogue
    const int lm = lane >> 2, lc = (lane & 3) << 1;
    float2 bs[8];
    #pragma unroll
    for (int nt = 0; nt < 8; nt++)
        bs[nt] = *(const float2*)(bias + bn + wn + nt * 8 + lc);

    #pragma unroll
    for (int tm = 0; tm < 2; tm++)
        #pragma unroll
        for (int g = 0; g < 2; g++) {
            const int row = bm + wm + tm * 16 + g * 8 + lm;
            #pragma unroll
            for (int nt = 0; nt < 8; nt++) {
                const int col = bn + wn + nt * 8 + lc;
                float v0 = acc[tm][nt][g * 2 + 0] + bs[nt].x;
                float v1 = acc[tm][nt][g * 2 + 1] + bs[nt].y;
                if (MODE == 1) {
                    float2 cv = *(const float2*)(Cres + (size_t)row * N + col);
                    v0 += cv.x; v1 += cv.y;
                }
                if (MODE == 2) { v0 = fmaxf(v0, 0.f); v1 = fmaxf(v1, 0.f); }
                if (SPLIT) {
                    __nv_bfloat16 h0,l0,h1,l1;
                    split1(v0, h0, l0); split1(v1, h1, l1);
                    *(__nv_bfloat162*)(Dhi + (size_t)row * N + col) = __halves2bfloat162(h0, h1);
                    *(__nv_bfloat162*)(Dlo + (size_t)row * N + col) = __halves2bfloat162(l0, l1);
                } else {
                    *(float2*)(Dout + (size_t)row * N + col) = make_float2(v0, v1);
                }
            }
        }
}

// ---------------- attention over 3 keys + residual + LN1 --------------------
__global__ __launch_bounds__(256)
void attn_ln1_kernel(const float* __restrict__ q,
                     const float* __restrict__ k0, const float* __restrict__ k1,
                     const float* __restrict__ k2,
                     const float* __restrict__ v0, const float* __restrict__ v1,
                     const float* __restrict__ v2,
                     const float* __restrict__ dom,
                     const float* __restrict__ gam, const float* __restrict__ bet,
                     float* __restrict__ x,
                     __nv_bfloat162* __restrict__ xh, __nv_bfloat162* __restrict__ xl)
{
    const int b = blockIdx.x;
    const int t = threadIdx.x;
    const size_t off = (size_t)b * DIM + 4 * t;

    float4 q4 = *(const float4*)(q  + off);
    float4 ka = *(const float4*)(k0 + off);
    float4 kb = *(const float4*)(k1 + off);
    float4 kc = *(const float4*)(k2 + off);

    float s0 = q4.x*ka.x + q4.y*ka.y + q4.z*ka.z + q4.w*ka.w;
    float s1 = q4.x*kb.x + q4.y*kb.y + q4.z*kb.z + q4.w*kb.w;
    float s2 = q4.x*kc.x + q4.y*kc.y + q4.z*kc.z + q4.w*kc.w;

    #pragma unroll
    for (int o = 8; o; o >>= 1) {
        s0 += __shfl_xor_sync(0xffffffffu, s0, o, 16);
        s1 += __shfl_xor_sync(0xffffffffu, s1, o, 16);
        s2 += __shfl_xor_sync(0xffffffffu, s2, o, 16);
    }
    const float sc = 0.125f;
    s0 *= sc; s1 *= sc; s2 *= sc;
    float mx = fmaxf(s0, fmaxf(s1, s2));
    float e0 = expf(s0 - mx), e1 = expf(s1 - mx), e2 = expf(s2 - mx);
    float inv = 1.0f / (e0 + e1 + e2);
    e0 *= inv; e1 *= inv; e2 *= inv;

    float4 va = *(const float4*)(v0 + off);
    float4 vb = *(const float4*)(v1 + off);
    float4 vc = *(const float4*)(v2 + off);
    float4 d4 = *(const float4*)(dom + off);

    float4 r;
    r.x = d4.x + e0*va.x + e1*vb.x + e2*vc.x;
    r.y = d4.y + e0*va.y + e1*vb.y + e2*vc.y;
    r.z = d4.z + e0*va.z + e1*vb.z + e2*vc.z;
    r.w = d4.w + e0*va.w + e1*vb.w + e2*vc.w;

    float sum = r.x + r.y + r.z + r.w;
    float sq  = r.x*r.x + r.y*r.y + r.z*r.z + r.w*r.w;
    #pragma unroll
    for (int o = 16; o; o >>= 1) {
        sum += __shfl_xor_sync(0xffffffffu, sum, o);
        sq  += __shfl_xor_sync(0xffffffffu, sq,  o);
    }
    __shared__ float red[16];
    const int w = t >> 5;
    if ((t & 31) == 0) { red[w] = sum; red[8 + w] = sq; }
    __syncthreads();
    if (t == 0) {
        float a = 0.f, c = 0.f;
        #pragma unroll
        for (int i = 0; i < 8; i++) { a += red[i]; c += red[8 + i]; }
        red[0] = a; red[8] = c;
    }
    __syncthreads();
    sum = red[0]; sq = red[8];

    const float mu  = sum * (1.0f / DIM);
    const float var = sq * (1.0f / DIM) - mu * mu;
    const float rs  = rsqrtf(var + 1e-5f);

    float4 gg = *(const float4*)(gam + 4 * t);
    float4 bb = *(const float4*)(bet + 4 * t);
    float4 xo;
    xo.x = (r.x - mu) * rs * gg.x + bb.x;
    xo.y = (r.y - mu) * rs * gg.y + bb.y;
    xo.z = (r.z - mu) * rs * gg.z + bb.z;
    xo.w = (r.w - mu) * rs * gg.w + bb.w;
    *(float4*)(x + off) = xo;

    __nv_bfloat16 h0,h1,h2,h3,l0,l1,l2,l3;
    split1(xo.x,h0,l0); split1(xo.y,h1,l1); split1(xo.z,h2,l2); split1(xo.w,h3,l3);
    xh[off/2]   = __halves2bfloat162(h0,h1);
    xh[off/2+1] = __halves2bfloat162(h2,h3);
    xl[off/2]   = __halves2bfloat162(l0,l1);
    xl[off/2+1] = __halves2bfloat162(l2,l3);
}

// ---------------- LN2 + 3-logit head + softmax ------------------------------
__global__ __launch_bounds__(256)
void ln2_head_kernel(const float* __restrict__ y,
                     const float* __restrict__ gam, const float* __restrict__ bet,
                     const float* __restrict__ Ww, const float* __restrict__ bw,
                     float* __restrict__ out)
{
    const int b = blockIdx.x;
    const int t = threadIdx.x;
    const size_t off = (size_t)b * DIM + 4 * t;

    float4 r = *(const float4*)(y + off);
    float sum = r.x + r.y + r.z + r.w;
    float sq  = r.x*r.x + r.y*r.y + r.z*r.z + r.w*r.w;
    #pragma unroll
    for (int o = 16; o; o >>= 1) {
        sum += __shfl_xor_sync(0xffffffffu, sum, o);
        sq  += __shfl_xor_sync(0xffffffffu, sq,  o);
    }
    __shared__ float red[24];
    const int w = t >> 5;
    if ((t & 31) == 0) { red[w] = sum; red[8 + w] = sq; }
    __syncthreads();
    if (t == 0) {
        float a = 0.f, c = 0.f;
        #pragma unroll
        for (int i = 0; i < 8; i++) { a += red[i]; c += red[8 + i]; }
        red[0] = a; red[8] = c;
    }
    __syncthreads();
    sum = red[0]; sq = red[8];

    const float mu  = sum * (1.0f / DIM);
    const float var = sq * (1.0f / DIM) - mu * mu;
    const float rs  = rsqrtf(var + 1e-5f);

    float4 gg = *(const float4*)(gam + 4 * t);
    float4 bb = *(const float4*)(bet + 4 * t);
    float xn[4];
    xn[0] = (r.x - mu) * rs * gg.x + bb.x;
    xn[1] = (r.y - mu) * rs * gg.y + bb.y;
    xn[2] = (r.z - mu) * rs * gg.z + bb.z;
    xn[3] = (r.w - mu) * rs * gg.w + bb.w;

    float l0 = 0.f, l1 = 0.f, l2 = 0.f;
    const int base = 4 * t;
    #pragma unroll
    for (int e = 0; e < 4; e++) {
        const float* wr = Ww + (size_t)(base + e) * 3;
        l0 += xn[e] * wr[0];
        l1 += xn[e] * wr[1];
        l2 += xn[e] * wr[2];
    }
    #pragma unroll
    for (int o = 16; o; o >>= 1) {
        l0 += __shfl_xor_sync(0xffffffffu, l0, o);
        l1 += __shfl_xor_sync(0xffffffffu, l1, o);
        l2 += __shfl_xor_sync(0xffffffffu, l2, o);
    }
    __syncthreads();
    if ((t & 31) == 0) { red[w] = l0; red[8 + w] = l1; red[16 + w] = l2; }
    __syncthreads();
    if (t == 0) {
        float a = 0.f, c = 0.f, d = 0.f;
        #pragma unroll
        for (int i = 0; i < 8; i++) { a += red[i]; c += red[8 + i]; d += red[16 + i]; }
        a += bw[0]; c += bw[1]; d += bw[2];
        float m = fmaxf(a, fmaxf(c, d));
        float e0 = expf(a - m), e1 = expf(c - m), e2 = expf(d - m);
        float inv = 1.0f / (e0 + e1 + e2);
        out[3 * (size_t)b + 0] = e0 * inv;
        out[3 * (size_t)b + 1] = e1 * inv;
        out[3 * (size_t)b + 2] = e2 * inv;
    }
}

// ---------------- launch ----------------------------------------------------
extern "C" void kernel_launch(void* const* d_in, const int* in_sizes, int n_in,
                              void* d_out, int out_size)
{
    const float* m0   = (const float*)d_in[0];
    const float* m1   = (const float*)d_in[1];
    const float* m2   = (const float*)d_in[2];
    const float* dom  = (const float*)d_in[3];
    const float* Wg   = (const float*)d_in[4];
    const float* bg   = (const float*)d_in[5];
    const float* Wq   = (const float*)d_in[6];
    const float* bq   = (const float*)d_in[7];
    const float* Wk   = (const float*)d_in[8];
    const float* bk   = (const float*)d_in[9];
    const float* Wv   = (const float*)d_in[10];
    const float* bv   = (const float*)d_in[11];
    const float* W1   = (const float*)d_in[12];
    const float* b1   = (const float*)d_in[13];
    const float* W2   = (const float*)d_in[14];
    const float* b2   = (const float*)d_in[15];
    const float* gm1  = (const float*)d_in[16];
    const float* bt1  = (const float*)d_in[17];
    const float* gm2  = (const float*)d_in[18];
    const float* bt2  = (const float*)d_in[19];
    const float* Ww   = (const float*)d_in[20];
    const float* bw   = (const float*)d_in[21];
    float* out = (float*)d_out;

    __nv_bfloat16 *mavgh,*mavgl,*m0h,*m0l,*m1h,*m1l,*m2h,*m2l,*qinh,*qinl,*xh,*xl,*h1h,*h1l;
    __nv_bfloat16 *Wgth,*Wgtl,*Wqth,*Wqtl,*Wkth,*Wktl,*Wvth,*Wvtl,*W1th,*W1tl,*W2th,*W2tl;
    float *q,*k0,*k1,*k2,*v0,*v1,*v2,*x,*y;
    cudaGetSymbolAddress((void**)&mavgh, g_mavgh); cudaGetSymbolAddress((void**)&mavgl, g_mavgl);
    cudaGetSymbolAddress((void**)&m0h, g_m0h); cudaGetSymbolAddress((void**)&m0l, g_m0l);
    cudaGetSymbolAddress((void**)&m1h, g_m1h); cudaGetSymbolAddress((void**)&m1l, g_m1l);
    cudaGetSymbolAddress((void**)&m2h, g_m2h); cudaGetSymbolAddress((void**)&m2l, g_m2l);
    cudaGetSymbolAddress((void**)&qinh, g_qinh); cudaGetSymbolAddress((void**)&qinl, g_qinl);
    cudaGetSymbolAddress((void**)&xh, g_xh); cudaGetSymbolAddress((void**)&xl, g_xl);
    cudaGetSymbolAddress((void**)&h1h, g_h1h); cudaGetSymbolAddress((void**)&h1l, g_h1l);
    cudaGetSymbolAddress((void**)&Wgth, g_Wgth); cudaGetSymbolAddress((void**)&Wgtl, g_Wgtl);
    cudaGetSymbolAddress((void**)&Wqth, g_Wqth); cudaGetSymbolAddress((void**)&Wqtl, g_Wqtl);
    cudaGetSymbolAddress((void**)&Wkth, g_Wkth); cudaGetSymbolAddress((void**)&Wktl, g_Wktl);
    cudaGetSymbolAddress((void**)&Wvth, g_Wvth); cudaGetSymbolAddress((void**)&Wvtl, g_Wvtl);
    cudaGetSymbolAddress((void**)&W1th, g_W1th); cudaGetSymbolAddress((void**)&W1tl, g_W1tl);
    cudaGetSymbolAddress((void**)&W2th, g_W2th); cudaGetSymbolAddress((void**)&W2tl, g_W2tl);
    cudaGetSymbolAddress((void**)&q,  g_q);
    cudaGetSymbolAddress((void**)&k0, g_k0); cudaGetSymbolAddress((void**)&k1, g_k1);
    cudaGetSymbolAddress((void**)&k2, g_k2);
    cudaGetSymbolAddress((void**)&v0, g_v0); cudaGetSymbolAddress((void**)&v1, g_v1);
    cudaGetSymbolAddress((void**)&v2, g_v2);
    cudaGetSymbolAddress((void**)&x,  g_x);  cudaGetSymbolAddress((void**)&y,  g_y);

    cudaFuncSetAttribute(mma_gemm<0,false>, cudaFuncAttributeMaxDynamicSharedMemorySize, SMEM_SZ);
    cudaFuncSetAttribute(mma_gemm<1,true>,  cudaFuncAttributeMaxDynamicSharedMemorySize, SMEM_SZ);
    cudaFuncSetAttribute(mma_gemm<2,true>,  cudaFuncAttributeMaxDynamicSharedMemorySize, SMEM_SZ);
    cudaFuncSetAttribute(mma_gemm<1,false>, cudaFuncAttributeMaxDynamicSharedMemorySize, SMEM_SZ);

    // weight transpose + split
    dim3 wb(32, 8);
    wtrans_kernel<<<dim3(DIM/32, DIM/32), wb>>>(Wg, Wgth, Wgtl, DIM, DIM);
    wtrans_kernel<<<dim3(DIM/32, DIM/32), wb>>>(Wq, Wqth, Wqtl, DIM, DIM);
    wtrans_kernel<<<dim3(DIM/32, DIM/32), wb>>>(Wk, Wkth, Wktl, DIM, DIM);
    wtrans_kernel<<<dim3(DIM/32, DIM/32), wb>>>(Wv, Wvth, Wvtl, DIM, DIM);
    wtrans_kernel<<<dim3(FFN/32, DIM/32), wb>>>(W1, W1th, W1tl, DIM, FFN);
    wtrans_kernel<<<dim3(DIM/32, FFN/32), wb>>>(W2, W2th, W2tl, FFN, DIM);

    // activation splits + mavg (single pass over m0/m1/m2)
    const int n4 = BATCH * DIM / 4;
    prep_kernel<<<(n4+255)/256, 256>>>((const float4*)m0, (const float4*)m1, (const float4*)m2,
                                       (__nv_bfloat162*)m0h, (__nv_bfloat162*)m0l,
                                       (__nv_bfloat162*)m1h, (__nv_bfloat162*)m1l,
                                       (__nv_bfloat162*)m2h, (__nv_bfloat162*)m2l,
                                       (__nv_bfloat162*)mavgh, (__nv_bfloat162*)mavgl, n4);

    dim3 gd(DIM/128, BATCH/128);   // (8, 128)
    dim3 gf(FFN/128, BATCH/128);   // (32, 128)

    // qin = mavg@Wg + bg + dom  -> bf16 hi/lo (feeds Wq GEMM)
    mma_gemm<1,true ><<<gd, 256, SMEM_SZ>>>(mavgh, mavgl, Wgth, Wgtl, bg, dom,
                                            nullptr, qinh, qinl, DIM, DIM);
    // q = qin@Wq + bq  (fp32)
    mma_gemm<0,false><<<gd, 256, SMEM_SZ>>>(qinh, qinl, Wqth, Wqtl, bq, nullptr,
                                            q, nullptr, nullptr, DIM, DIM);
    // k_i / v_i
    mma_gemm<0,false><<<gd, 256, SMEM_SZ>>>(m0h, m0l, Wkth, Wktl, bk, nullptr, k0, nullptr, nullptr, DIM, DIM);
    mma_gemm<0,false><<<gd, 256, SMEM_SZ>>>(m1h, m1l, Wkth, Wktl, bk, nullptr, k1, nullptr, nullptr, DIM, DIM);
    mma_gemm<0,false><<<gd, 256, SMEM_SZ>>>(m2h, m2l, Wkth, Wktl, bk, nullptr, k2, nullptr, nullptr, DIM, DIM);
    mma_gemm<0,false><<<gd, 256, SMEM_SZ>>>(m0h, m0l, Wvth, Wvtl, bv, nullptr, v0, nullptr, nullptr, DIM, DIM);
    mma_gemm<0,false><<<gd, 256, SMEM_SZ>>>(m1h, m1l, Wvth, Wvtl, bv, nullptr, v1, nullptr, nullptr, DIM, DIM);
    mma_gemm<0,false><<<gd, 256, SMEM_SZ>>>(m2h, m2l, Wvth, Wvtl, bv, nullptr, v2, nullptr, nullptr, DIM, DIM);

    // attention + residual + LN1 -> x (fp32) and x hi/lo (bf16)
    attn_ln1_kernel<<<BATCH, 256>>>(q, k0, k1, k2, v0, v1, v2, dom, gm1, bt1, x,
                                    (__nv_bfloat162*)xh, (__nv_bfloat162*)xl);

    // h1 = relu(x@W1 + b1) -> bf16 hi/lo
    mma_gemm<2,true ><<<gf, 256, SMEM_SZ>>>(xh, xl, W1th, W1tl, b1, nullptr,
                                            nullptr, h1h, h1l, FFN, DIM);
    // y = x + h1@W2 + b2  (fp32)
    mma_gemm<1,false><<<gd, 256, SMEM_SZ>>>(h1h, h1l, W2th, W2tl, b2, x,
                                            y, nullptr, nullptr, DIM, FFN);

    // LN2 + head + softmax
    ln2_head_kernel<<<BATCH, 256>>>(y, gm2, bt2, Ww, bw, out);
}

// round 4
// speedup vs baseline: 7.8223x; 2.4685x over previous
#include <cuda_runtime.h>
#include <cuda_fp16.h>
#include <stdint.h>
#include <math.h>

#define BATCH 16384
#define DIM   1024
#define FFN   4096

#define NB ((size_t)BATCH * DIM)
#define NF ((size_t)BATCH * FFN)

// ---------------- scratch (static device globals; no runtime allocs) -------
__device__ __half g_mavgh[NB];
__device__ __half g_m0h[NB], g_m1h[NB], g_m2h[NB];
__device__ __half g_qinh[NB];
__device__ __half g_xh[NB];
__device__ __half g_h1h[NF];
// transposed weights, [N,K] K-major, fp16
__device__ __half g_Wgth[(size_t)DIM*DIM];
__device__ __half g_Wqth[(size_t)DIM*DIM];
__device__ __half g_Wkth[(size_t)DIM*DIM];
__device__ __half g_Wvth[(size_t)DIM*DIM];
__device__ __half g_W1th[(size_t)DIM*FFN];
__device__ __half g_W2th[(size_t)DIM*FFN];
// fp32 intermediates
__device__ float g_q[NB], g_k0[NB], g_k1[NB], g_k2[NB];
__device__ float g_v0[NB], g_v1[NB], g_v2[NB];
__device__ float g_x[NB], g_y[NB];

// ---------------- helpers ----------------------------------------------------
__device__ __forceinline__ uint32_t s2u(const void* p) {
    uint32_t a;
    asm("{ .reg .u64 t; cvta.to.shared.u64 t, %1; cvt.u32.u64 %0, t; }" : "=r"(a) : "l"(p));
    return a;
}
__device__ __forceinline__ void cp16(uint32_t s, const void* g) {
    asm volatile("cp.async.cg.shared.global [%0], [%1], 16;" :: "r"(s), "l"(g));
}
#define SWZ(o) ((o) ^ (((o) >> 3) & 0x70))

__device__ __forceinline__ void ldsm4(uint32_t addr, uint32_t* r) {
    asm volatile("ldmatrix.sync.aligned.m8n8.x4.shared.b16 {%0,%1,%2,%3}, [%4];"
        : "=r"(r[0]), "=r"(r[1]), "=r"(r[2]), "=r"(r[3]) : "r"(addr));
}
__device__ __forceinline__ void mma16816(float* c, const uint32_t* a, const uint32_t* b) {
    asm volatile(
        "mma.sync.aligned.m16n8k16.row.col.f32.f16.f16.f32 "
        "{%0,%1,%2,%3}, {%4,%5,%6,%7}, {%8,%9}, {%0,%1,%2,%3};"
        : "+f"(c[0]), "+f"(c[1]), "+f"(c[2]), "+f"(c[3])
        : "r"(a[0]), "r"(a[1]), "r"(a[2]), "r"(a[3]), "r"(b[0]), "r"(b[1]));
}

// ---------------- prep: convert m0/m1/m2 + mavg to fp16 (single pass) -------
__global__ void prep_kernel(const float4* __restrict__ m0, const float4* __restrict__ m1,
                            const float4* __restrict__ m2,
                            __half2* __restrict__ m0h, __half2* __restrict__ m1h,
                            __half2* __restrict__ m2h, __half2* __restrict__ avh,
                            int n4)
{
    int i = blockIdx.x * blockDim.x + threadIdx.x;
    if (i >= n4) return;
    float4 a = m0[i], b = m1[i], c = m2[i];
    const float s = 1.0f / 3.0f;
    float4 v;
    v.x = (a.x+b.x+c.x)*s; v.y = (a.y+b.y+c.y)*s;
    v.z = (a.z+b.z+c.z)*s; v.w = (a.w+b.w+c.w)*s;
    m0h[2*i]   = __floats2half2_rn(a.x, a.y);
    m0h[2*i+1] = __floats2half2_rn(a.z, a.w);
    m1h[2*i]   = __floats2half2_rn(b.x, b.y);
    m1h[2*i+1] = __floats2half2_rn(b.z, b.w);
    m2h[2*i]   = __floats2half2_rn(c.x, c.y);
    m2h[2*i+1] = __floats2half2_rn(c.z, c.w);
    avh[2*i]   = __floats2half2_rn(v.x, v.y);
    avh[2*i+1] = __floats2half2_rn(v.z, v.w);
}

// weights: W[K,N] fp32 -> out [N,K] fp16 (transpose + convert)
__global__ void wtrans_kernel(const float* __restrict__ W,
                              __half* __restrict__ H, int K, int N)
{
    __shared__ float t[32][33];
    const int k0 = blockIdx.y << 5, n0 = blockIdx.x << 5;
    const int tx = threadIdx.x, ty = threadIdx.y;
    #pragma unroll
    for (int r = 0; r < 32; r += 8)
        t[ty + r][tx] = W[(size_t)(k0 + ty + r) * N + n0 + tx];
    __syncthreads();
    #pragma unroll
    for (int r = 0; r < 32; r += 8)
        H[(size_t)(n0 + ty + r) * K + k0 + tx] = __float2half(t[tx][ty + r]);
}

// ---------------- single-pass fp16 HMMA GEMM ---------------------------------
// D[M,N] = A[M,K] @ B[N,K]^T + bias (+C) (relu)
// MODE 0: +bias; MODE 1: +bias+C; MODE 2: relu(+bias)
// CVT: also/instead write fp16 output
#define STAGE_SZ 32768
#define SMEM_SZ  (3 * STAGE_SZ)

// load one 128x64 fp16 tile (row-major [*,K]) into SW128-swizzled SMEM (256 thr)
__device__ __forceinline__ void ldtile(uint32_t sbase, const __half* g, int ldk, int tid) {
    #pragma unroll
    for (int i = 0; i < 4; i++) {
        int idx = tid + (i << 8);
        int row = idx >> 3, ks = idx & 7;
        cp16(sbase + SWZ(row * 128 + ks * 16), g + (size_t)row * ldk + ks * 8);
    }
}

template<int MODE, bool CVT>
__global__ __launch_bounds__(256, 2)
void mma_gemm(const __half* __restrict__ A, const __half* __restrict__ B,
              const float* __restrict__ bias, const float* __restrict__ Cres,
              float* __restrict__ Dout, __half* __restrict__ Dh,
              int N, int K)
{
    extern __shared__ char smem[];
    const uint32_t sb = s2u(smem);
    const int tid = threadIdx.x;
    const int wid = tid >> 5, lane = tid & 31;
    const int bm = blockIdx.y << 7, bn = blockIdx.x << 7;
    const int wm = (wid >> 1) << 5;   // warp row offset 0/32/64/96
    const int wn = (wid & 1) << 6;    // warp col offset 0/64
    const int nch = K >> 6;

    const __half* Ap = A + (size_t)bm * K;
    const __half* Bp = B + (size_t)bn * K;

    // prologue: chunks 0,1 -> stages 0,1
    #pragma unroll
    for (int c = 0; c < 2; c++) {
        uint32_t st = sb + c * STAGE_SZ;
        ldtile(st,         Ap + c * 64, K, tid);
        ldtile(st + 16384, Bp + c * 64, K, tid);
        asm volatile("cp.async.commit_group;" ::: "memory");
    }

    float acc[2][8][4];
    #pragma unroll
    for (int a = 0; a < 2; a++)
        #pragma unroll
        for (int b = 0; b < 8; b++)
            #pragma unroll
            for (int d = 0; d < 4; d++) acc[a][b][d] = 0.0f;

    // ldmatrix per-lane addressing
    const int aRow = wm + (lane & 15);
    const int aKB  = ((lane >> 4) & 1) * 16;
    const int bj   = lane >> 3;
    const int bRow = wn + ((bj >> 1) << 3) + (lane & 7);
    const int bKB  = (bj & 1) * 16;

    for (int i = 0; i < nch; i++) {
        if (i < nch - 1) asm volatile("cp.async.wait_group 1;" ::: "memory");
        else             asm volatile("cp.async.wait_group 0;" ::: "memory");
        __syncthreads();

        // prefetch chunk i+2 (overlaps with compute below)
        const int pc = i + 2;
        if (pc < nch) {
            uint32_t pt = sb + (pc % 3) * STAGE_SZ;
            ldtile(pt,         Ap + pc * 64, K, tid);
            ldtile(pt + 16384, Bp + pc * 64, K, tid);
            asm volatile("cp.async.commit_group;" ::: "memory");
        }

        const uint32_t st = sb + (i % 3) * STAGE_SZ;
        #pragma unroll
        for (int kk = 0; kk < 4; kk++) {
            uint32_t aR[2][4];
            #pragma unroll
            for (int tm = 0; tm < 2; tm++) {
                uint32_t off = SWZ((uint32_t)((aRow + tm * 16) * 128 + kk * 32 + aKB));
                ldsm4(st + off, aR[tm]);
            }
            uint32_t bR[4][4];
            #pragma unroll
            for (int p = 0; p < 4; p++) {
                uint32_t off = SWZ((uint32_t)((bRow + p * 16) * 128 + kk * 32 + bKB));
                ldsm4(st + 16384 + off, bR[p]);
            }
            #pragma unroll
            for (int tm = 0; tm < 2; tm++)
                #pragma unroll
                for (int p = 0; p < 4; p++) {
                    mma16816(acc[tm][2*p],     aR[tm], &bR[p][0]);
                    mma16816(acc[tm][2*p + 1], aR[tm], &bR[p][2]);
                }
        }
    }

    // epilogue
    const int lm = lane >> 2, lc = (lane & 3) << 1;
    float2 bs[8];
    #pragma unroll
    for (int nt = 0; nt < 8; nt++)
        bs[nt] = *(const float2*)(bias + bn + wn + nt * 8 + lc);

    #pragma unroll
    for (int tm = 0; tm < 2; tm++)
        #pragma unroll
        for (int g = 0; g < 2; g++) {
            const int row = bm + wm + tm * 16 + g * 8 + lm;
            #pragma unroll
            for (int nt = 0; nt < 8; nt++) {
                const int col = bn + wn + nt * 8 + lc;
                float v0 = acc[tm][nt][g * 2 + 0] + bs[nt].x;
                float v1 = acc[tm][nt][g * 2 + 1] + bs[nt].y;
                if (MODE == 1) {
                    float2 cv = *(const float2*)(Cres + (size_t)row * N + col);
                    v0 += cv.x; v1 += cv.y;
                }
                if (MODE == 2) { v0 = fmaxf(v0, 0.f); v1 = fmaxf(v1, 0.f); }
                if (CVT)
                    *(__half2*)(Dh + (size_t)row * N + col) = __floats2half2_rn(v0, v1);
                else
                    *(float2*)(Dout + (size_t)row * N + col) = make_float2(v0, v1);
            }
        }
}

// ---------------- attention over 3 keys + residual + LN1 --------------------
__global__ __launch_bounds__(256)
void attn_ln1_kernel(const float* __restrict__ q,
                     const float* __restrict__ k0, const float* __restrict__ k1,
                     const float* __restrict__ k2,
                     const float* __restrict__ v0, const float* __restrict__ v1,
                     const float* __restrict__ v2,
                     const float* __restrict__ dom,
                     const float* __restrict__ gam, const float* __restrict__ bet,
                     float* __restrict__ x, __half2* __restrict__ xh)
{
    const int b = blockIdx.x;
    const int t = threadIdx.x;
    const size_t off = (size_t)b * DIM + 4 * t;

    float4 q4 = *(const float4*)(q  + off);
    float4 ka = *(const float4*)(k0 + off);
    float4 kb = *(const float4*)(k1 + off);
    float4 kc = *(const float4*)(k2 + off);

    float s0 = q4.x*ka.x + q4.y*ka.y + q4.z*ka.z + q4.w*ka.w;
    float s1 = q4.x*kb.x + q4.y*kb.y + q4.z*kb.z + q4.w*kb.w;
    float s2 = q4.x*kc.x + q4.y*kc.y + q4.z*kc.z + q4.w*kc.w;

    #pragma unroll
    for (int o = 8; o; o >>= 1) {
        s0 += __shfl_xor_sync(0xffffffffu, s0, o, 16);
        s1 += __shfl_xor_sync(0xffffffffu, s1, o, 16);
        s2 += __shfl_xor_sync(0xffffffffu, s2, o, 16);
    }
    const float sc = 0.125f;
    s0 *= sc; s1 *= sc; s2 *= sc;
    float mx = fmaxf(s0, fmaxf(s1, s2));
    float e0 = expf(s0 - mx), e1 = expf(s1 - mx), e2 = expf(s2 - mx);
    float inv = 1.0f / (e0 + e1 + e2);
    e0 *= inv; e1 *= inv; e2 *= inv;

    float4 va = *(const float4*)(v0 + off);
    float4 vb = *(const float4*)(v1 + off);
    float4 vc = *(const float4*)(v2 + off);
    float4 d4 = *(const float4*)(dom + off);

    float4 r;
    r.x = d4.x + e0*va.x + e1*vb.x + e2*vc.x;
    r.y = d4.y + e0*va.y + e1*vb.y + e2*vc.y;
    r.z = d4.z + e0*va.z + e1*vb.z + e2*vc.z;
    r.w = d4.w + e0*va.w + e1*vb.w + e2*vc.w;

    float sum = r.x + r.y + r.z + r.w;
    float sq  = r.x*r.x + r.y*r.y + r.z*r.z + r.w*r.w;
    #pragma unroll
    for (int o = 16; o; o >>= 1) {
        sum += __shfl_xor_sync(0xffffffffu, sum, o);
        sq  += __shfl_xor_sync(0xffffffffu, sq,  o);
    }
    __shared__ float red[16];
    const int w = t >> 5;
    if ((t & 31) == 0) { red[w] = sum; red[8 + w] = sq; }
    __syncthreads();
    if (t == 0) {
        float a = 0.f, c = 0.f;
        #pragma unroll
        for (int i = 0; i < 8; i++) { a += red[i]; c += red[8 + i]; }
        red[0] = a; red[8] = c;
    }
    __syncthreads();
    sum = red[0]; sq = red[8];

    const float mu  = sum * (1.0f / DIM);
    const float var = sq * (1.0f / DIM) - mu * mu;
    const float rs  = rsqrtf(var + 1e-5f);

    float4 gg = *(const float4*)(gam + 4 * t);
    float4 bb = *(const float4*)(bet + 4 * t);
    float4 xo;
    xo.x = (r.x - mu) * rs * gg.x + bb.x;
    xo.y = (r.y - mu) * rs * gg.y + bb.y;
    xo.z = (r.z - mu) * rs * gg.z + bb.z;
    xo.w = (r.w - mu) * rs * gg.w + bb.w;
    *(float4*)(x + off) = xo;
    xh[off/2]   = __floats2half2_rn(xo.x, xo.y);
    xh[off/2+1] = __floats2half2_rn(xo.z, xo.w);
}

// ---------------- LN2 + 3-logit head + softmax ------------------------------
__global__ __launch_bounds__(256)
void ln2_head_kernel(const float* __restrict__ y,
                     const float* __restrict__ gam, const float* __restrict__ bet,
                     const float* __restrict__ Ww, const float* __restrict__ bw,
                     float* __restrict__ out)
{
    const int b = blockIdx.x;
    const int t = threadIdx.x;
    const size_t off = (size_t)b * DIM + 4 * t;

    float4 r = *(const float4*)(y + off);
    float sum = r.x + r.y + r.z + r.w;
    float sq  = r.x*r.x + r.y*r.y + r.z*r.z + r.w*r.w;
    #pragma unroll
    for (int o = 16; o; o >>= 1) {
        sum += __shfl_xor_sync(0xffffffffu, sum, o);
        sq  += __shfl_xor_sync(0xffffffffu, sq,  o);
    }
    __shared__ float red[24];
    const int w = t >> 5;
    if ((t & 31) == 0) { red[w] = sum; red[8 + w] = sq; }
    __syncthreads();
    if (t == 0) {
        float a = 0.f, c = 0.f;
        #pragma unroll
        for (int i = 0; i < 8; i++) { a += red[i]; c += red[8 + i]; }
        red[0] = a; red[8] = c;
    }
    __syncthreads();
    sum = red[0]; sq = red[8];

    const float mu  = sum * (1.0f / DIM);
    const float var = sq * (1.0f / DIM) - mu * mu;
    const float rs  = rsqrtf(var + 1e-5f);

    float4 gg = *(const float4*)(gam + 4 * t);
    float4 bb = *(const float4*)(bet + 4 * t);
    float xn[4];
    xn[0] = (r.x - mu) * rs * gg.x + bb.x;
    xn[1] = (r.y - mu) * rs * gg.y + bb.y;
    xn[2] = (r.z - mu) * rs * gg.z + bb.z;
    xn[3] = (r.w - mu) * rs * gg.w + bb.w;

    float l0 = 0.f, l1 = 0.f, l2 = 0.f;
    const int base = 4 * t;
    #pragma unroll
    for (int e = 0; e < 4; e++) {
        const float* wr = Ww + (size_t)(base + e) * 3;
        l0 += xn[e] * wr[0];
        l1 += xn[e] * wr[1];
        l2 += xn[e] * wr[2];
    }
    #pragma unroll
    for (int o = 16; o; o >>= 1) {
        l0 += __shfl_xor_sync(0xffffffffu, l0, o);
        l1 += __shfl_xor_sync(0xffffffffu, l1, o);
        l2 += __shfl_xor_sync(0xffffffffu, l2, o);
    }
    __syncthreads();
    if ((t & 31) == 0) { red[w] = l0; red[8 + w] = l1; red[16 + w] = l2; }
    __syncthreads();
    if (t == 0) {
        float a = 0.f, c = 0.f, d = 0.f;
        #pragma unroll
        for (int i = 0; i < 8; i++) { a += red[i]; c += red[8 + i]; d += red[16 + i]; }
        a += bw[0]; c += bw[1]; d += bw[2];
        float m = fmaxf(a, fmaxf(c, d));
        float e0 = expf(a - m), e1 = expf(c - m), e2 = expf(d - m);
        float inv = 1.0f / (e0 + e1 + e2);
        out[3 * (size_t)b + 0] = e0 * inv;
        out[3 * (size_t)b + 1] = e1 * inv;
        out[3 * (size_t)b + 2] = e2 * inv;
    }
}

// ---------------- launch ----------------------------------------------------
extern "C" void kernel_launch(void* const* d_in, const int* in_sizes, int n_in,
                              void* d_out, int out_size)
{
    const float* m0   = (const float*)d_in[0];
    const float* m1   = (const float*)d_in[1];
    const float* m2   = (const float*)d_in[2];
    const float* dom  = (const float*)d_in[3];
    const float* Wg   = (const float*)d_in[4];
    const float* bg   = (const float*)d_in[5];
    const float* Wq   = (const float*)d_in[6];
    const float* bq   = (const float*)d_in[7];
    const float* Wk   = (const float*)d_in[8];
    const float* bk   = (const float*)d_in[9];
    const float* Wv   = (const float*)d_in[10];
    const float* bv   = (const float*)d_in[11];
    const float* W1   = (const float*)d_in[12];
    const float* b1   = (const float*)d_in[13];
    const float* W2   = (const float*)d_in[14];
    const float* b2   = (const float*)d_in[15];
    const float* gm1  = (const float*)d_in[16];
    const float* bt1  = (const float*)d_in[17];
    const float* gm2  = (const float*)d_in[18];
    const float* bt2  = (const float*)d_in[19];
    const float* Ww   = (const float*)d_in[20];
    const float* bw   = (const float*)d_in[21];
    float* out = (float*)d_out;

    __half *mavgh,*m0h,*m1h,*m2h,*qinh,*xh,*h1h;
    __half *Wgth,*Wqth,*Wkth,*Wvth,*W1th,*W2th;
    float *q,*k0,*k1,*k2,*v0,*v1,*v2,*x,*y;
    cudaGetSymbolAddress((void**)&mavgh, g_mavgh);
    cudaGetSymbolAddress((void**)&m0h, g_m0h);
    cudaGetSymbolAddress((void**)&m1h, g_m1h);
    cudaGetSymbolAddress((void**)&m2h, g_m2h);
    cudaGetSymbolAddress((void**)&qinh, g_qinh);
    cudaGetSymbolAddress((void**)&xh, g_xh);
    cudaGetSymbolAddress((void**)&h1h, g_h1h);
    cudaGetSymbolAddress((void**)&Wgth, g_Wgth);
    cudaGetSymbolAddress((void**)&Wqth, g_Wqth);
    cudaGetSymbolAddress((void**)&Wkth, g_Wkth);
    cudaGetSymbolAddress((void**)&Wvth, g_Wvth);
    cudaGetSymbolAddress((void**)&W1th, g_W1th);
    cudaGetSymbolAddress((void**)&W2th, g_W2th);
    cudaGetSymbolAddress((void**)&q,  g_q);
    cudaGetSymbolAddress((void**)&k0, g_k0); cudaGetSymbolAddress((void**)&k1, g_k1);
    cudaGetSymbolAddress((void**)&k2, g_k2);
    cudaGetSymbolAddress((void**)&v0, g_v0); cudaGetSymbolAddress((void**)&v1, g_v1);
    cudaGetSymbolAddress((void**)&v2, g_v2);
    cudaGetSymbolAddress((void**)&x,  g_x);  cudaGetSymbolAddress((void**)&y,  g_y);

    cudaFuncSetAttribute(mma_gemm<0,false>, cudaFuncAttributeMaxDynamicSharedMemorySize, SMEM_SZ);
    cudaFuncSetAttribute(mma_gemm<1,true>,  cudaFuncAttributeMaxDynamicSharedMemorySize, SMEM_SZ);
    cudaFuncSetAttribute(mma_gemm<2,true>,  cudaFuncAttributeMaxDynamicSharedMemorySize, SMEM_SZ);
    cudaFuncSetAttribute(mma_gemm<1,false>, cudaFuncAttributeMaxDynamicSharedMemorySize, SMEM_SZ);

    // weight transpose + convert
    dim3 wb(32, 8);
    wtrans_kernel<<<dim3(DIM/32, DIM/32), wb>>>(Wg, Wgth, DIM, DIM);
    wtrans_kernel<<<dim3(DIM/32, DIM/32), wb>>>(Wq, Wqth, DIM, DIM);
    wtrans_kernel<<<dim3(DIM/32, DIM/32), wb>>>(Wk, Wkth, DIM, DIM);
    wtrans_kernel<<<dim3(DIM/32, DIM/32), wb>>>(Wv, Wvth, DIM, DIM);
    wtrans_kernel<<<dim3(FFN/32, DIM/32), wb>>>(W1, W1th, DIM, FFN);
    wtrans_kernel<<<dim3(DIM/32, FFN/32), wb>>>(W2, W2th, FFN, DIM);

    // activation converts + mavg (single pass over m0/m1/m2)
    const int n4 = BATCH * DIM / 4;
    prep_kernel<<<(n4+255)/256, 256>>>((const float4*)m0, (const float4*)m1, (const float4*)m2,
                                       (__half2*)m0h, (__half2*)m1h, (__half2*)m2h,
                                       (__half2*)mavgh, n4);

    dim3 gd(DIM/128, BATCH/128);   // (8, 128)
    dim3 gf(FFN/128, BATCH/128);   // (32, 128)

    // qin = mavg@Wg + bg + dom  -> fp16 (feeds Wq GEMM)
    mma_gemm<1,true ><<<gd, 256, SMEM_SZ>>>(mavgh, Wgth, bg, dom, nullptr, qinh, DIM, DIM);
    // q = qin@Wq + bq  (fp32)
    mma_gemm<0,false><<<gd, 256, SMEM_SZ>>>(qinh, Wqth, bq, nullptr, q, nullptr, DIM, DIM);
    // k_i / v_i
    mma_gemm<0,false><<<gd, 256, SMEM_SZ>>>(m0h, Wkth, bk, nullptr, k0, nullptr, DIM, DIM);
    mma_gemm<0,false><<<gd, 256, SMEM_SZ>>>(m1h, Wkth, bk, nullptr, k1, nullptr, DIM, DIM);
    mma_gemm<0,false><<<gd, 256, SMEM_SZ>>>(m2h, Wkth, bk, nullptr, k2, nullptr, DIM, DIM);
    mma_gemm<0,false><<<gd, 256, SMEM_SZ>>>(m0h, Wvth, bv, nullptr, v0, nullptr, DIM, DIM);
    mma_gemm<0,false><<<gd, 256, SMEM_SZ>>>(m1h, Wvth, bv, nullptr, v1, nullptr, DIM, DIM);
    mma_gemm<0,false><<<gd, 256, SMEM_SZ>>>(m2h, Wvth, bv, nullptr, v2, nullptr, DIM, DIM);

    // attention + residual + LN1 -> x (fp32) and xh (fp16)
    attn_ln1_kernel<<<BATCH, 256>>>(q, k0, k1, k2, v0, v1, v2, dom, gm1, bt1, x,
                                    (__half2*)xh);

    // h1 = relu(x@W1 + b1) -> fp16
    mma_gemm<2,true ><<<gf, 256, SMEM_SZ>>>(xh, W1th, b1, nullptr, nullptr, h1h, FFN, DIM);
    // y = x + h1@W2 + b2  (fp32)
    mma_gemm<1,false><<<gd, 256, SMEM_SZ>>>(h1h, W2th, b2, x, y, nullptr, DIM, FFN);

    // LN2 + head + softmax
    ln2_head_kernel<<<BATCH, 256>>>(y, gm2, bt2, Ww, bw, out);
}